// round 3
// baseline (speedup 1.0000x reference)
#include <cuda_runtime.h>
#include <cuda_bf16.h>
#include <cstdint>

#define LSEQ 252
#define HID 768
#define MLP 770
#define NLAB 36
#define BATCH 2
#define KP 784            // MLP padded to 98*8
#define NPH1 1540         // 2*MLP
#define MROWS 504         // BATCH*LSEQ
#define LL (LSEQ*LSEQ)    // 63504
#define W1STRIDE 1537     // 2*HID+1

// ---- scratch (device globals; no dynamic allocation allowed) ----
__device__ float g_W1r[NPH1 * HID];          // repacked W1 (col-major B operand rows)
__device__ float g_Ai[MROWS * KP];           // Ai, zero-padded cols [770,784)
__device__ float g_Aj[MROWS * KP];
__device__ float g_Cc[3 * KP];               // b1 + c*w1c, c=0..2
__device__ __nv_bfloat16 g_W2b[40 * KP];     // W2 padded to 40x784, bf16
__device__ float g_lse[BATCH * NLAB];

// ---------------------------------------------------------------------------
// tf32 mma m16n8k8 (row.col), fp32 accum
__device__ __forceinline__ void mma_tf32(float* d, float a0, float a1, float a2, float a3,
                                         float b0, float b1) {
    asm volatile(
        "mma.sync.aligned.m16n8k8.row.col.f32.tf32.tf32.f32 "
        "{%0,%1,%2,%3},{%4,%5,%6,%7},{%8,%9},{%0,%1,%2,%3};\n"
        : "+f"(d[0]), "+f"(d[1]), "+f"(d[2]), "+f"(d[3])
        : "r"(__float_as_uint(a0)), "r"(__float_as_uint(a1)),
          "r"(__float_as_uint(a2)), "r"(__float_as_uint(a3)),
          "r"(__float_as_uint(b0)), "r"(__float_as_uint(b1)));
}

// ---------------------------------------------------------------------------
// Prep: repack W1 -> g_W1r, build C vectors, bf16 W2, zero pad cols of Ai/Aj.
__global__ void k_prep(const float* __restrict__ W1, const float* __restrict__ b1,
                       const float* __restrict__ W2) {
    int idx = blockIdx.x * blockDim.x + threadIdx.x;
    int stride = gridDim.x * blockDim.x;
    for (int t = idx; t < NPH1 * HID; t += stride) {
        int n = t / HID, k = t - n * HID;
        g_W1r[t] = (n < MLP) ? W1[n * W1STRIDE + k] : W1[(n - MLP) * W1STRIDE + HID + k];
    }
    for (int t = idx; t < 3 * KP; t += stride) {
        int c = t / KP, h = t - c * KP;
        g_Cc[t] = (h < MLP) ? (b1[h] + (float)c * W1[h * W1STRIDE + 2 * HID]) : 0.0f;
    }
    for (int t = idx; t < 40 * KP; t += stride) {
        int n = t / KP, k = t - n * KP;
        float v = (n < NLAB && k < MLP) ? W2[n * MLP + k] : 0.0f;
        g_W2b[t] = __float2bfloat16(v);
    }
    for (int t = idx; t < MROWS * (KP - MLP); t += stride) {
        int m = t / (KP - MLP), c = MLP + (t - m * (KP - MLP));
        g_Ai[m * KP + c] = 0.0f;
        g_Aj[m * KP + c] = 0.0f;
    }
}

// ---------------------------------------------------------------------------
// Phase 1: [504x768] @ [768x1540] tf32 GEMM -> g_Ai / g_Aj (fp32).
// Block tile 64x64, 4 warps (2x2), warp tile 32x32, k-chunk 32.
__global__ __launch_bounds__(128) void k_ph1(const float* __restrict__ hidden) {
    __shared__ float As[64 * 36];
    __shared__ float Bs[64 * 36];
    const int tid = threadIdx.x, lane = tid & 31, w = tid >> 5;
    const int m0 = blockIdx.y * 64, n0 = blockIdx.x * 64;
    const int wm = w >> 1, wn = w & 1;
    const int r = lane >> 2, kq = lane & 3;

    float acc[2][4][4];
#pragma unroll
    for (int a = 0; a < 2; a++)
#pragma unroll
        for (int b = 0; b < 4; b++)
#pragma unroll
            for (int c = 0; c < 4; c++) acc[a][b][c] = 0.0f;

    for (int kc = 0; kc < 24; kc++) {
        const int k0 = kc * 32;
#pragma unroll
        for (int p = 0; p < 4; p++) {
            int i = tid + p * 128;
            int row = i >> 3, c8 = i & 7;
            int m = m0 + row;
            float4 v = make_float4(0.f, 0.f, 0.f, 0.f);
            if (m < MROWS) {
                int b = m / LSEQ, l = m - b * LSEQ;
                v = *(const float4*)&hidden[((size_t)(b * (LSEQ + 1) + l + 1)) * HID + k0 + c8 * 4];
            }
            *(float4*)&As[row * 36 + c8 * 4] = v;
        }
#pragma unroll
        for (int p = 0; p < 4; p++) {
            int i = tid + p * 128;
            int row = i >> 3, c8 = i & 7;
            int n = n0 + row;
            float4 v = make_float4(0.f, 0.f, 0.f, 0.f);
            if (n < NPH1) v = *(const float4*)&g_W1r[(size_t)n * HID + k0 + c8 * 4];
            *(float4*)&Bs[row * 36 + c8 * 4] = v;
        }
        __syncthreads();
#pragma unroll
        for (int kk = 0; kk < 4; kk++) {
            const int kb = kk * 8 + kq;
            float a[2][4];
#pragma unroll
            for (int mf = 0; mf < 2; mf++) {
                int rb = wm * 32 + mf * 16 + r;
                a[mf][0] = As[rb * 36 + kb];
                a[mf][1] = As[(rb + 8) * 36 + kb];
                a[mf][2] = As[rb * 36 + kb + 4];
                a[mf][3] = As[(rb + 8) * 36 + kb + 4];
            }
#pragma unroll
            for (int nf = 0; nf < 4; nf++) {
                int nr = wn * 32 + nf * 8 + r;
                float b0 = Bs[nr * 36 + kb];
                float b1 = Bs[nr * 36 + kb + 4];
                mma_tf32(acc[0][nf], a[0][0], a[0][1], a[0][2], a[0][3], b0, b1);
                mma_tf32(acc[1][nf], a[1][0], a[1][1], a[1][2], a[1][3], b0, b1);
            }
        }
        __syncthreads();
    }
    // epilogue: remap n<770 -> Ai, else Aj
#pragma unroll
    for (int mf = 0; mf < 2; mf++) {
#pragma unroll
        for (int nf = 0; nf < 4; nf++) {
            int mg = m0 + wm * 32 + mf * 16 + r;
            int ng = n0 + wn * 32 + nf * 8 + kq * 2;
            if (ng < NPH1) {
                float* dst = (ng < MLP) ? &g_Ai[0] + (size_t)0 : &g_Aj[0];
                int col = (ng < MLP) ? ng : ng - MLP;
                if (mg < MROWS) {
                    float2 v = make_float2(acc[mf][nf][0], acc[mf][nf][1]);
                    *(float2*)&dst[(size_t)mg * KP + col] = v;
                }
                if (mg + 8 < MROWS) {
                    float2 v = make_float2(acc[mf][nf][2], acc[mf][nf][3]);
                    *(float2*)&dst[(size_t)(mg + 8) * KP + col] = v;
                }
            }
        }
    }
}

// ---------------------------------------------------------------------------
// Main fused kernel: block = 4 i's x 32 j's, 8 warps, each warp one 16-row
// m-tile over all 5 n-tiles. A operand generated in fragment layout from smem.
#define AJ_STRIDE 796
#define W2_STRIDE 792
#define SMEM_MAIN ((32 * AJ_STRIDE + 12 * AJ_STRIDE) * 4 + 40 * W2_STRIDE * 2 + 128)

__global__ __launch_bounds__(256, 1) void k_main(const int* __restrict__ spans,
                                                 const int* __restrict__ smask,
                                                 const float* __restrict__ b2,
                                                 float* __restrict__ out) {
    extern __shared__ char smem[];
    float* AjS = (float*)smem;                                   // [32][796]
    float* AiC = AjS + 32 * AJ_STRIDE;                           // [4][3][796]
    __nv_bfloat16* W2s = (__nv_bfloat16*)(AiC + 12 * AJ_STRIDE); // [40][792]
    unsigned char* cf = (unsigned char*)(W2s + 40 * W2_STRIDE);  // [4][32]

    const int tid = threadIdx.x;
    const int b = blockIdx.z, it = blockIdx.y, jt = blockIdx.x;
    const int i0 = it * 4, j0 = jt * 32;
    const int s = spans[b * 2], e = spans[b * 2 + 1];

    // Aj tile
    for (int t = tid; t < 32 * 196; t += 256) {
        int row = t / 196, c4 = t - row * 196;
        int j = j0 + row;
        float4 v = make_float4(0.f, 0.f, 0.f, 0.f);
        if (j < LSEQ) v = *(const float4*)&g_Aj[(size_t)(b * LSEQ + j) * KP + c4 * 4];
        *(float4*)&AjS[row * AJ_STRIDE + c4 * 4] = v;
    }
    // AiC = Ai[i0+il] + Cc[c]
    for (int t = tid; t < 12 * 196; t += 256) {
        int rc = t / 196, c4 = t - rc * 196;
        int il = rc / 3, c = rc - il * 3;
        float4 va = *(const float4*)&g_Ai[(size_t)(b * LSEQ + i0 + il) * KP + c4 * 4];
        float4 vc = *(const float4*)&g_Cc[c * KP + c4 * 4];
        float4 o = make_float4(va.x + vc.x, va.y + vc.y, va.z + vc.z, va.w + vc.w);
        *(float4*)&AiC[rc * AJ_STRIDE + c4 * 4] = o;
    }
    // W2 tile (bf16)
    for (int t = tid; t < 40 * 98; t += 256) {
        int row = t / 98, c = t - row * 98;
        uint4 v = *(const uint4*)&g_W2b[row * KP + c * 8];
        *(uint4*)((char*)W2s + (size_t)row * W2_STRIDE * 2 + c * 16) = v;
    }
    // c / valid flags
    for (int t = tid; t < 4 * 32; t += 256) {
        int il = t >> 5, jl = t & 31;
        int i = i0 + il, j = j0 + jl;
        int c = 0, valid = 0;
        if (j < LSEQ) {
            valid = (smask[i * LSEQ + j] >= 1) ? 1 : 0;
            if (s <= i && i <= j && j <= e) c = (i == s && j == e) ? 2 : 1;
        }
        cf[t] = (unsigned char)(c | (valid << 2));
    }
    __syncthreads();

    const int lane = tid & 31, w = tid >> 5;
    const int il = w >> 1, j0l = (w & 1) * 16;
    const int r = lane >> 2, kq = lane & 3;
    const int jr0 = j0l + r, jr1 = jr0 + 8;
    const int f0 = cf[il * 32 + jr0], f1 = cf[il * 32 + jr1];

    const float* aj0 = AjS + jr0 * AJ_STRIDE + kq;
    const float* aj1 = AjS + jr1 * AJ_STRIDE + kq;
    const float* ac0 = AiC + (il * 3 + (f0 & 3)) * AJ_STRIDE + kq;
    const float* ac1 = AiC + (il * 3 + (f1 & 3)) * AJ_STRIDE + kq;
    const __nv_bfloat16* wp = W2s + r * W2_STRIDE + kq;

    float acc[5][4];
#pragma unroll
    for (int nt = 0; nt < 5; nt++)
#pragma unroll
        for (int q = 0; q < 4; q++) acc[nt][q] = 0.0f;

#pragma unroll 2
    for (int ks = 0; ks < 98; ks++) {
        const int off = ks * 8;
        float a0 = fmaxf(aj0[off] + ac0[off], 0.0f);
        float a1 = fmaxf(aj1[off] + ac1[off], 0.0f);
        float a2 = fmaxf(aj0[off + 4] + ac0[off + 4], 0.0f);
        float a3 = fmaxf(aj1[off + 4] + ac1[off + 4], 0.0f);
#pragma unroll
        for (int nt = 0; nt < 5; nt++) {
            float b0 = __bfloat162float(wp[nt * 8 * W2_STRIDE + off]);
            float b1 = __bfloat162float(wp[nt * 8 * W2_STRIDE + off + 4]);
            mma_tf32(acc[nt], a0, a1, a2, a3, b0, b1);
        }
    }

    // epilogue: +b2, mask, store into out[b][k][i*252+j]
    const int i = i0 + il;
    const int jg0 = j0 + jr0, jg1 = j0 + jr1;
    const int v0 = (f0 >> 2) & 1, v1 = (f1 >> 2) & 1;
#pragma unroll
    for (int nt = 0; nt < 5; nt++) {
        int k0 = nt * 8 + kq * 2;
        if (k0 < NLAB) {
            float bb0 = b2[k0], bb1 = b2[k0 + 1];
            if (jg0 < LSEQ) {
                size_t p0 = (size_t)(b * NLAB + k0) * LL + i * LSEQ + jg0;
                out[p0] = v0 ? (acc[nt][0] + bb0) : 0.0f;
                out[p0 + LL] = v0 ? (acc[nt][1] + bb1) : 0.0f;
            }
            if (jg1 < LSEQ) {
                size_t p1 = (size_t)(b * NLAB + k0) * LL + i * LSEQ + jg1;
                out[p1] = v1 ? (acc[nt][2] + bb0) : 0.0f;
                out[p1 + LL] = v1 ? (acc[nt][3] + bb1) : 0.0f;
            }
        }
    }
}

// ---------------------------------------------------------------------------
// log-sum-exp per (b,k)
__global__ void k_lse(const float* __restrict__ out) {
    const int bk = blockIdx.x;  // 0..71
    const float* p = out + (size_t)bk * LL;
    const int tid = threadIdx.x;
    float m = -1e30f, sum = 0.0f;
    for (int idx = tid; idx < LL; idx += 256) {
        float x = p[idx];
        if (x > m) {
            sum = sum * expf(m - x) + 1.0f;
            m = x;
        } else {
            sum += expf(x - m);
        }
    }
    __shared__ float sm[256], ss[256];
    sm[tid] = m;
    ss[tid] = sum;
    __syncthreads();
    for (int st = 128; st > 0; st >>= 1) {
        if (tid < st) {
            float m2 = sm[tid + st], s2 = ss[tid + st];
            float M = fmaxf(sm[tid], m2);
            ss[tid] = ss[tid] * expf(sm[tid] - M) + s2 * expf(m2 - M);
            sm[tid] = M;
        }
        __syncthreads();
    }
    if (tid == 0) g_lse[bk] = sm[0] + logf(ss[0]);
}

__global__ void k_sub(float* __restrict__ out) {
    const int bk = blockIdx.y;
    const int idx = blockIdx.x * 256 + threadIdx.x;
    if (idx < LL) out[(size_t)bk * LL + idx] -= g_lse[bk];
}

// ---------------------------------------------------------------------------
extern "C" void kernel_launch(void* const* d_in, const int* in_sizes, int n_in,
                              void* d_out, int out_size) {
    const float* hidden = (const float*)d_in[0];
    const int* spans = (const int*)d_in[1];
    const int* smask = (const int*)d_in[2];
    const float* W1 = (const float*)d_in[3];
    const float* b1 = (const float*)d_in[4];
    const float* W2 = (const float*)d_in[5];
    const float* b2 = (const float*)d_in[6];
    float* out = (float*)d_out;

    cudaFuncSetAttribute(k_main, cudaFuncAttributeMaxDynamicSharedMemorySize, SMEM_MAIN);

    k_prep<<<256, 256>>>(W1, b1, W2);
    k_ph1<<<dim3(25, 8), 128>>>(hidden);
    k_main<<<dim3(8, 63, 2), 256, SMEM_MAIN>>>(spans, smask, b2, out);
    k_lse<<<72, 256>>>(out);
    k_sub<<<dim3((LL + 255) / 256, BATCH * NLAB), 256>>>(out);
}

// round 5
// speedup vs baseline: 1.2283x; 1.2283x over previous
#include <cuda_runtime.h>
#include <cuda_bf16.h>
#include <cstdint>

#define LSEQ 252
#define HID 768
#define MLP 770
#define NLAB 36
#define BATCH 2
#define KP 784            // MLP padded to 98*8
#define NPH1 1540         // 2*MLP
#define MROWS 504         // BATCH*LSEQ
#define LL (LSEQ*LSEQ)    // 63504
#define LL4 (LL/4)        // 15876
#define W1STRIDE 1537     // 2*HID+1

// ---- scratch (device globals; no dynamic allocation allowed) ----
__device__ float g_W1r[NPH1 * HID];          // repacked W1 (col-major B operand rows)
__device__ float g_Ai[MROWS * KP];           // Ai, zero-padded cols [770,784)
__device__ float g_Aj[MROWS * KP];
__device__ float g_Cc[3 * KP];               // b1 + c*w1c, c=0..2
__device__ __nv_bfloat16 g_W2b[40 * KP];     // W2 padded to 40x784, bf16
__device__ unsigned g_maxbits[BATCH * NLAB]; // per-(b,k) max (>=0, as float bits)
__device__ float g_psum[BATCH * NLAB * 8];   // partial exp-sums

// ---------------------------------------------------------------------------
// tf32 mma m16n8k8 (row.col), fp32 accum
__device__ __forceinline__ void mma_tf32(float* d, float a0, float a1, float a2, float a3,
                                         float b0, float b1) {
    asm volatile(
        "mma.sync.aligned.m16n8k8.row.col.f32.tf32.tf32.f32 "
        "{%0,%1,%2,%3},{%4,%5,%6,%7},{%8,%9},{%0,%1,%2,%3};\n"
        : "+f"(d[0]), "+f"(d[1]), "+f"(d[2]), "+f"(d[3])
        : "r"(__float_as_uint(a0)), "r"(__float_as_uint(a1)),
          "r"(__float_as_uint(a2)), "r"(__float_as_uint(a3)),
          "r"(__float_as_uint(b0)), "r"(__float_as_uint(b1)));
}

// ---------------------------------------------------------------------------
// Prep: repack W1 -> g_W1r, build C vectors, bf16 W2, zero pad cols, reset max.
__global__ void k_prep(const float* __restrict__ W1, const float* __restrict__ b1,
                       const float* __restrict__ W2) {
    int idx = blockIdx.x * blockDim.x + threadIdx.x;
    int stride = gridDim.x * blockDim.x;
    for (int t = idx; t < NPH1 * HID; t += stride) {
        int n = t / HID, k = t - n * HID;
        g_W1r[t] = (n < MLP) ? W1[n * W1STRIDE + k] : W1[(n - MLP) * W1STRIDE + HID + k];
    }
    for (int t = idx; t < 3 * KP; t += stride) {
        int c = t / KP, h = t - c * KP;
        g_Cc[t] = (h < MLP) ? (b1[h] + (float)c * W1[h * W1STRIDE + 2 * HID]) : 0.0f;
    }
    for (int t = idx; t < 40 * KP; t += stride) {
        int n = t / KP, k = t - n * KP;
        float v = (n < NLAB && k < MLP) ? W2[n * MLP + k] : 0.0f;
        g_W2b[t] = __float2bfloat16(v);
    }
    for (int t = idx; t < MROWS * (KP - MLP); t += stride) {
        int m = t / (KP - MLP), c = MLP + (t - m * (KP - MLP));
        g_Ai[m * KP + c] = 0.0f;
        g_Aj[m * KP + c] = 0.0f;
    }
    for (int t = idx; t < BATCH * NLAB; t += stride) g_maxbits[t] = 0u;
}

// ---------------------------------------------------------------------------
// Phase 1: [504x768] @ [768x1540] tf32 GEMM -> g_Ai / g_Aj (fp32).
__global__ __launch_bounds__(128) void k_ph1(const float* __restrict__ hidden) {
    __shared__ float As[64 * 36];
    __shared__ float Bs[64 * 36];
    const int tid = threadIdx.x, lane = tid & 31, w = tid >> 5;
    const int m0 = blockIdx.y * 64, n0 = blockIdx.x * 64;
    const int wm = w >> 1, wn = w & 1;
    const int r = lane >> 2, kq = lane & 3;

    float acc[2][4][4];
#pragma unroll
    for (int a = 0; a < 2; a++)
#pragma unroll
        for (int b = 0; b < 4; b++)
#pragma unroll
            for (int c = 0; c < 4; c++) acc[a][b][c] = 0.0f;

    for (int kc = 0; kc < 24; kc++) {
        const int k0 = kc * 32;
#pragma unroll
        for (int p = 0; p < 4; p++) {
            int i = tid + p * 128;
            int row = i >> 3, c8 = i & 7;
            int m = m0 + row;
            float4 v = make_float4(0.f, 0.f, 0.f, 0.f);
            if (m < MROWS) {
                int b = m / LSEQ, l = m - b * LSEQ;
                v = *(const float4*)&hidden[((size_t)(b * (LSEQ + 1) + l + 1)) * HID + k0 + c8 * 4];
            }
            *(float4*)&As[row * 36 + c8 * 4] = v;
        }
#pragma unroll
        for (int p = 0; p < 4; p++) {
            int i = tid + p * 128;
            int row = i >> 3, c8 = i & 7;
            int n = n0 + row;
            float4 v = make_float4(0.f, 0.f, 0.f, 0.f);
            if (n < NPH1) v = *(const float4*)&g_W1r[(size_t)n * HID + k0 + c8 * 4];
            *(float4*)&Bs[row * 36 + c8 * 4] = v;
        }
        __syncthreads();
#pragma unroll
        for (int kk = 0; kk < 4; kk++) {
            const int kb = kk * 8 + kq;
            float a[2][4];
#pragma unroll
            for (int mf = 0; mf < 2; mf++) {
                int rb = wm * 32 + mf * 16 + r;
                a[mf][0] = As[rb * 36 + kb];
                a[mf][1] = As[(rb + 8) * 36 + kb];
                a[mf][2] = As[rb * 36 + kb + 4];
                a[mf][3] = As[(rb + 8) * 36 + kb + 4];
            }
#pragma unroll
            for (int nf = 0; nf < 4; nf++) {
                int nr = wn * 32 + nf * 8 + r;
                float b0 = Bs[nr * 36 + kb];
                float b1 = Bs[nr * 36 + kb + 4];
                mma_tf32(acc[0][nf], a[0][0], a[0][1], a[0][2], a[0][3], b0, b1);
                mma_tf32(acc[1][nf], a[1][0], a[1][1], a[1][2], a[1][3], b0, b1);
            }
        }
        __syncthreads();
    }
#pragma unroll
    for (int mf = 0; mf < 2; mf++) {
#pragma unroll
        for (int nf = 0; nf < 4; nf++) {
            int mg = m0 + wm * 32 + mf * 16 + r;
            int ng = n0 + wn * 32 + nf * 8 + kq * 2;
            if (ng < NPH1) {
                float* dst = (ng < MLP) ? &g_Ai[0] : &g_Aj[0];
                int col = (ng < MLP) ? ng : ng - MLP;
                if (mg < MROWS) {
                    float2 v = make_float2(acc[mf][nf][0], acc[mf][nf][1]);
                    *(float2*)&dst[(size_t)mg * KP + col] = v;
                }
                if (mg + 8 < MROWS) {
                    float2 v = make_float2(acc[mf][nf][2], acc[mf][nf][3]);
                    *(float2*)&dst[(size_t)(mg + 8) * KP + col] = v;
                }
            }
        }
    }
}

// ---------------------------------------------------------------------------
// Main fused kernel. Smem columns stored pair-permuted: within each group of 8
// cols, order is [c0,c4,c1,c5,c2,c6,c3,c7] so fragment pairs (kq, kq+4) are
// adjacent -> LDS.64 for A halves, LDS.U32 bf16x2 for B pairs.
#define AJ_STRIDE 808   // floats; ==8 mod 32 -> conflict-free 64-bit phases
#define W2S 840         // halves; bank = 4r+kq, all 32 lanes distinct
#define SMEM_MAIN ((32 * AJ_STRIDE + 12 * AJ_STRIDE) * 4 + 40 * W2S * 2 + 128)

__global__ __launch_bounds__(256, 1) void k_main(const int* __restrict__ spans,
                                                 const int* __restrict__ smask,
                                                 const float* __restrict__ b2,
                                                 float* __restrict__ out) {
    extern __shared__ char smem[];
    float* AjS = (float*)smem;                                   // [32][808]
    float* AiC = AjS + 32 * AJ_STRIDE;                           // [4][3][808]
    __nv_bfloat16* W2s = (__nv_bfloat16*)(AiC + 12 * AJ_STRIDE); // [40][840]
    unsigned char* cf = (unsigned char*)((char*)W2s + 40 * W2S * 2); // [4][32]

    const int tid = threadIdx.x;
    const int b = blockIdx.z, it = blockIdx.y, jt = blockIdx.x;
    const int i0 = it * 4, j0 = jt * 32;
    const int s = spans[b * 2], e = spans[b * 2 + 1];

    // Aj tile (pair-permuted)
    for (int u = tid; u < 32 * 98; u += 256) {
        int row = u / 98, g = u - row * 98;
        int j = j0 + row;
        float4 v0 = make_float4(0.f, 0.f, 0.f, 0.f), v1 = v0;
        if (j < LSEQ) {
            const float4* src = (const float4*)&g_Aj[(size_t)(b * LSEQ + j) * KP + g * 8];
            v0 = src[0];
            v1 = src[1];
        }
        float4* dst = (float4*)&AjS[row * AJ_STRIDE + g * 8];
        dst[0] = make_float4(v0.x, v1.x, v0.y, v1.y);
        dst[1] = make_float4(v0.z, v1.z, v0.w, v1.w);
    }
    // AiC = Ai[i0+il] + Cc[c] (pair-permuted)
    for (int u = tid; u < 12 * 98; u += 256) {
        int rc = u / 98, g = u - rc * 98;
        int il = rc / 3, c = rc - il * 3;
        const float4* sa = (const float4*)&g_Ai[(size_t)(b * LSEQ + i0 + il) * KP + g * 8];
        const float4* sc = (const float4*)&g_Cc[c * KP + g * 8];
        float4 a0 = sa[0], a1 = sa[1], c0 = sc[0], c1 = sc[1];
        float4 x = make_float4(a0.x + c0.x, a0.y + c0.y, a0.z + c0.z, a0.w + c0.w);
        float4 y = make_float4(a1.x + c1.x, a1.y + c1.y, a1.z + c1.z, a1.w + c1.w);
        float4* dst = (float4*)&AiC[rc * AJ_STRIDE + g * 8];
        dst[0] = make_float4(x.x, y.x, x.y, y.y);
        dst[1] = make_float4(x.z, y.z, x.w, y.w);
    }
    // W2 tile (bf16, pair-permuted via PRMT)
    for (int u = tid; u < 40 * 98; u += 256) {
        int row = u / 98, g = u - row * 98;
        uint4 v = *(const uint4*)&g_W2b[row * KP + g * 8];
        unsigned o0 = __byte_perm(v.x, v.z, 0x5410);  // (h0,h4)
        unsigned o1 = __byte_perm(v.x, v.z, 0x7632);  // (h1,h5)
        unsigned o2 = __byte_perm(v.y, v.w, 0x5410);  // (h2,h6)
        unsigned o3 = __byte_perm(v.y, v.w, 0x7632);  // (h3,h7)
        *(uint4*)((char*)W2s + ((size_t)row * W2S + g * 8) * 2) = make_uint4(o0, o1, o2, o3);
    }
    // c / valid flags
    for (int t = tid; t < 4 * 32; t += 256) {
        int il = t >> 5, jl = t & 31;
        int i = i0 + il, j = j0 + jl;
        int c = 0, valid = 0;
        if (j < LSEQ) {
            valid = (smask[i * LSEQ + j] >= 1) ? 1 : 0;
            if (s <= i && i <= j && j <= e) c = (i == s && j == e) ? 2 : 1;
        }
        cf[t] = (unsigned char)(c | (valid << 2));
    }
    __syncthreads();

    const int lane = tid & 31, w = tid >> 5;
    const int il = w >> 1, j0l = (w & 1) * 16;
    const int r = lane >> 2, kq = lane & 3;
    const int jr0 = j0l + r, jr1 = jr0 + 8;
    const int f0 = cf[il * 32 + jr0], f1 = cf[il * 32 + jr1];

    const float* aj0 = AjS + jr0 * AJ_STRIDE + 2 * kq;
    const float* aj1 = AjS + jr1 * AJ_STRIDE + 2 * kq;
    const float* ac0 = AiC + (il * 3 + (f0 & 3)) * AJ_STRIDE + 2 * kq;
    const float* ac1 = AiC + (il * 3 + (f1 & 3)) * AJ_STRIDE + 2 * kq;
    const char* wp = (const char*)W2s + ((size_t)r * W2S + 2 * kq) * 2;

    float acc[5][4];
#pragma unroll
    for (int nt = 0; nt < 5; nt++)
#pragma unroll
        for (int q = 0; q < 4; q++) acc[nt][q] = 0.0f;

#pragma unroll 2
    for (int ks = 0; ks < 98; ks++) {
        const int off = ks * 8;
        float2 pj0 = *(const float2*)(aj0 + off);
        float2 pc0 = *(const float2*)(ac0 + off);
        float2 pj1 = *(const float2*)(aj1 + off);
        float2 pc1 = *(const float2*)(ac1 + off);
        float a0 = fmaxf(pj0.x + pc0.x, 0.0f);
        float a2 = fmaxf(pj0.y + pc0.y, 0.0f);
        float a1 = fmaxf(pj1.x + pc1.x, 0.0f);
        float a3 = fmaxf(pj1.y + pc1.y, 0.0f);
#pragma unroll
        for (int nt = 0; nt < 5; nt++) {
            unsigned wv = *(const unsigned*)(wp + ((size_t)nt * 8 * W2S + off) * 2);
            float b0 = __uint_as_float(wv << 16);
            float b1 = __uint_as_float(wv & 0xFFFF0000u);
            mma_tf32(acc[nt], a0, a1, a2, a3, b0, b1);
        }
    }

    // epilogue: +b2, mask, store into out[b][k][i*252+j]
    const int i = i0 + il;
    const int jg0 = j0 + jr0, jg1 = j0 + jr1;
    const int v0 = (f0 >> 2) & 1, v1 = (f1 >> 2) & 1;
#pragma unroll
    for (int nt = 0; nt < 5; nt++) {
        int k0 = nt * 8 + kq * 2;
        if (k0 < NLAB) {
            float bb0 = b2[k0], bb1 = b2[k0 + 1];
            if (jg0 < LSEQ) {
                size_t p0 = (size_t)(b * NLAB + k0) * LL + i * LSEQ + jg0;
                out[p0] = v0 ? (acc[nt][0] + bb0) : 0.0f;
                out[p0 + LL] = v0 ? (acc[nt][1] + bb1) : 0.0f;
            }
            if (jg1 < LSEQ) {
                size_t p1 = (size_t)(b * NLAB + k0) * LL + i * LSEQ + jg1;
                out[p1] = v1 ? (acc[nt][2] + bb0) : 0.0f;
                out[p1 + LL] = v1 ? (acc[nt][3] + bb1) : 0.0f;
            }
        }
    }
}

// ---------------------------------------------------------------------------
// Pass A: per-(b,k) max (clamped at 0 — exact, since masked entries are 0).
__global__ __launch_bounds__(256) void k_maxp(const float* __restrict__ out) {
    const int bk = blockIdx.y;
    const float4* p = (const float4*)(out + (size_t)bk * LL);
    float m = 0.0f;
    for (int t = blockIdx.x * 256 + threadIdx.x; t < LL4; t += 8 * 256) {
        float4 v = p[t];
        m = fmaxf(m, fmaxf(fmaxf(v.x, v.y), fmaxf(v.z, v.w)));
    }
#pragma unroll
    for (int o = 16; o > 0; o >>= 1) m = fmaxf(m, __shfl_xor_sync(0xFFFFFFFFu, m, o));
    __shared__ float sm[8];
    if ((threadIdx.x & 31) == 0) sm[threadIdx.x >> 5] = m;
    __syncthreads();
    if (threadIdx.x == 0) {
        float mm = sm[0];
#pragma unroll
        for (int q = 1; q < 8; q++) mm = fmaxf(mm, sm[q]);
        atomicMax(&g_maxbits[bk], __float_as_uint(mm));  // mm >= 0: bit-monotone
    }
}

// Pass B: partial sum of exp(x - M); 4 independent accumulator chains.
__global__ __launch_bounds__(256) void k_sumexp(const float* __restrict__ out) {
    const int bk = blockIdx.y;
    const float4* p = (const float4*)(out + (size_t)bk * LL);
    const float M = __uint_as_float(g_maxbits[bk]);
    const float L2E = 1.4426950408889634f;
    const float nML2E = -M * L2E;
    float s0 = 0.f, s1 = 0.f, s2 = 0.f, s3 = 0.f;
    for (int t = blockIdx.x * 256 + threadIdx.x; t < LL4; t += 8 * 256) {
        float4 v = p[t];
        s0 += exp2f(fmaf(v.x, L2E, nML2E));
        s1 += exp2f(fmaf(v.y, L2E, nML2E));
        s2 += exp2f(fmaf(v.z, L2E, nML2E));
        s3 += exp2f(fmaf(v.w, L2E, nML2E));
    }
    float s = (s0 + s1) + (s2 + s3);
#pragma unroll
    for (int o = 16; o > 0; o >>= 1) s += __shfl_xor_sync(0xFFFFFFFFu, s, o);
    __shared__ float sm[8];
    if ((threadIdx.x & 31) == 0) sm[threadIdx.x >> 5] = s;
    __syncthreads();
    if (threadIdx.x == 0) {
        float ss = 0.f;
#pragma unroll
        for (int q = 0; q < 8; q++) ss += sm[q];
        g_psum[bk * 8 + blockIdx.x] = ss;  // fixed slot -> deterministic
    }
}

// Combine partials (fixed order) + subtract lse.
__global__ __launch_bounds__(256) void k_sub(float* __restrict__ out) {
    const int bk = blockIdx.y;
    __shared__ float lse_s;
    if (threadIdx.x == 0) {
        float M = __uint_as_float(g_maxbits[bk]);
        float s = 0.f;
#pragma unroll
        for (int q = 0; q < 8; q++) s += g_psum[bk * 8 + q];
        lse_s = M + logf(s);
    }
    __syncthreads();
    const float lse = lse_s;
    int t = blockIdx.x * 256 + threadIdx.x;
    if (t < LL4) {
        float4* p = (float4*)(out + (size_t)bk * LL);
        float4 v = p[t];
        v.x -= lse;
        v.y -= lse;
        v.z -= lse;
        v.w -= lse;
        p[t] = v;
    }
}

// ---------------------------------------------------------------------------
extern "C" void kernel_launch(void* const* d_in, const int* in_sizes, int n_in,
                              void* d_out, int out_size) {
    const float* hidden = (const float*)d_in[0];
    const int* spans = (const int*)d_in[1];
    const int* smask = (const int*)d_in[2];
    const float* W1 = (const float*)d_in[3];
    const float* b1 = (const float*)d_in[4];
    const float* W2 = (const float*)d_in[5];
    const float* b2 = (const float*)d_in[6];
    float* out = (float*)d_out;

    cudaFuncSetAttribute(k_main, cudaFuncAttributeMaxDynamicSharedMemorySize, SMEM_MAIN);

    k_prep<<<256, 256>>>(W1, b1, W2);
    k_ph1<<<dim3(25, 8), 128>>>(hidden);
    k_main<<<dim3(8, 63, 2), 256, SMEM_MAIN>>>(spans, smask, b2, out);
    k_maxp<<<dim3(8, BATCH * NLAB), 256>>>(out);
    k_sumexp<<<dim3(8, BATCH * NLAB), 256>>>(out);
    k_sub<<<dim3((LL4 + 255) / 256, BATCH * NLAB), 256>>>(out);
}

// round 8
// speedup vs baseline: 1.5401x; 1.2538x over previous
#include <cuda_runtime.h>
#include <cuda_bf16.h>
#include <cstdint>

#define LSEQ 252
#define HID 768
#define MLP 770
#define NLAB 36
#define BATCH 2
#define KP 784            // MLP padded to 98*8
#define NPH1 1540         // 2*MLP
#define MROWS 504         // BATCH*LSEQ
#define LL (LSEQ*LSEQ)    // 63504
#define LL4 (LL/4)        // 15876
#define W1STRIDE 1537     // 2*HID+1
#define NPART 16          // softmax partial-sum slots per (b,k)
#define NIT_PER 7         // it-values per persistent block (63 = 9*7)

// ---- scratch (device globals; no dynamic allocation allowed) ----
__device__ float g_W1r[NPH1 * HID];          // repacked W1 (col-major B operand rows)
__device__ float g_Ai[MROWS * KP];           // Ai, zero-padded cols [770,784)
__device__ float g_Aj[MROWS * KP];
__device__ float g_Cc[3 * KP];               // b1 + c*w1c, c=0..2
__device__ __nv_bfloat16 g_W2b[40 * KP];     // W2 padded to 40x784, bf16
__device__ unsigned g_maxbits[BATCH * NLAB]; // per-(b,k) max (>=0, as float bits)
__device__ float g_psum[BATCH * NLAB * NPART]; // partial exp-sums

// ---------------------------------------------------------------------------
// tf32 mma m16n8k8 (row.col), fp32 accum
__device__ __forceinline__ void mma_tf32(float* d, float a0, float a1, float a2, float a3,
                                         float b0, float b1) {
    asm volatile(
        "mma.sync.aligned.m16n8k8.row.col.f32.tf32.tf32.f32 "
        "{%0,%1,%2,%3},{%4,%5,%6,%7},{%8,%9},{%0,%1,%2,%3};\n"
        : "+f"(d[0]), "+f"(d[1]), "+f"(d[2]), "+f"(d[3])
        : "r"(__float_as_uint(a0)), "r"(__float_as_uint(a1)),
          "r"(__float_as_uint(a2)), "r"(__float_as_uint(a3)),
          "r"(__float_as_uint(b0)), "r"(__float_as_uint(b1)));
}

// ---------------------------------------------------------------------------
// Prep: repack W1 -> g_W1r, build C vectors, bf16 W2, zero pad cols, reset max.
__global__ void k_prep(const float* __restrict__ W1, const float* __restrict__ b1,
                       const float* __restrict__ W2) {
    int idx = blockIdx.x * blockDim.x + threadIdx.x;
    int stride = gridDim.x * blockDim.x;
    for (int t = idx; t < NPH1 * HID; t += stride) {
        int n = t / HID, k = t - n * HID;
        g_W1r[t] = (n < MLP) ? W1[n * W1STRIDE + k] : W1[(n - MLP) * W1STRIDE + HID + k];
    }
    for (int t = idx; t < 3 * KP; t += stride) {
        int c = t / KP, h = t - c * KP;
        g_Cc[t] = (h < MLP) ? (b1[h] + (float)c * W1[h * W1STRIDE + 2 * HID]) : 0.0f;
    }
    for (int t = idx; t < 40 * KP; t += stride) {
        int n = t / KP, k = t - n * KP;
        float v = (n < NLAB && k < MLP) ? W2[n * MLP + k] : 0.0f;
        g_W2b[t] = __float2bfloat16(v);
    }
    for (int t = idx; t < MROWS * (KP - MLP); t += stride) {
        int m = t / (KP - MLP), c = MLP + (t - m * (KP - MLP));
        g_Ai[m * KP + c] = 0.0f;
        g_Aj[m * KP + c] = 0.0f;
    }
    for (int t = idx; t < BATCH * NLAB; t += stride) g_maxbits[t] = 0u;
}

// ---------------------------------------------------------------------------
// Phase 1: [504x768] @ [768x1540] tf32 GEMM -> g_Ai / g_Aj (fp32).
__global__ __launch_bounds__(128) void k_ph1(const float* __restrict__ hidden) {
    __shared__ float As[64 * 36];
    __shared__ float Bs[64 * 36];
    const int tid = threadIdx.x, lane = tid & 31, w = tid >> 5;
    const int m0 = blockIdx.y * 64, n0 = blockIdx.x * 64;
    const int wm = w >> 1, wn = w & 1;
    const int r = lane >> 2, kq = lane & 3;

    float acc[2][4][4];
#pragma unroll
    for (int a = 0; a < 2; a++)
#pragma unroll
        for (int b = 0; b < 4; b++)
#pragma unroll
            for (int c = 0; c < 4; c++) acc[a][b][c] = 0.0f;

    for (int kc = 0; kc < 24; kc++) {
        const int k0 = kc * 32;
#pragma unroll
        for (int p = 0; p < 4; p++) {
            int i = tid + p * 128;
            int row = i >> 3, c8 = i & 7;
            int m = m0 + row;
            float4 v = make_float4(0.f, 0.f, 0.f, 0.f);
            if (m < MROWS) {
                int b = m / LSEQ, l = m - b * LSEQ;
                v = *(const float4*)&hidden[((size_t)(b * (LSEQ + 1) + l + 1)) * HID + k0 + c8 * 4];
            }
            *(float4*)&As[row * 36 + c8 * 4] = v;
        }
#pragma unroll
        for (int p = 0; p < 4; p++) {
            int i = tid + p * 128;
            int row = i >> 3, c8 = i & 7;
            int n = n0 + row;
            float4 v = make_float4(0.f, 0.f, 0.f, 0.f);
            if (n < NPH1) v = *(const float4*)&g_W1r[(size_t)n * HID + k0 + c8 * 4];
            *(float4*)&Bs[row * 36 + c8 * 4] = v;
        }
        __syncthreads();
#pragma unroll
        for (int kk = 0; kk < 4; kk++) {
            const int kb = kk * 8 + kq;
            float a[2][4];
#pragma unroll
            for (int mf = 0; mf < 2; mf++) {
                int rb = wm * 32 + mf * 16 + r;
                a[mf][0] = As[rb * 36 + kb];
                a[mf][1] = As[(rb + 8) * 36 + kb];
                a[mf][2] = As[rb * 36 + kb + 4];
                a[mf][3] = As[(rb + 8) * 36 + kb + 4];
            }
#pragma unroll
            for (int nf = 0; nf < 4; nf++) {
                int nr = wn * 32 + nf * 8 + r;
                float b0 = Bs[nr * 36 + kb];
                float b1 = Bs[nr * 36 + kb + 4];
                mma_tf32(acc[0][nf], a[0][0], a[0][1], a[0][2], a[0][3], b0, b1);
                mma_tf32(acc[1][nf], a[1][0], a[1][1], a[1][2], a[1][3], b0, b1);
            }
        }
        __syncthreads();
    }
#pragma unroll
    for (int mf = 0; mf < 2; mf++) {
#pragma unroll
        for (int nf = 0; nf < 4; nf++) {
            int mg = m0 + wm * 32 + mf * 16 + r;
            int ng = n0 + wn * 32 + nf * 8 + kq * 2;
            if (ng < NPH1) {
                float* dst = (ng < MLP) ? &g_Ai[0] : &g_Aj[0];
                int col = (ng < MLP) ? ng : ng - MLP;
                if (mg < MROWS) {
                    float2 v = make_float2(acc[mf][nf][0], acc[mf][nf][1]);
                    *(float2*)&dst[(size_t)mg * KP + col] = v;
                }
                if (mg + 8 < MROWS) {
                    float2 v = make_float2(acc[mf][nf][2], acc[mf][nf][3]);
                    *(float2*)&dst[(size_t)(mg + 8) * KP + col] = v;
                }
            }
        }
    }
}

// ---------------------------------------------------------------------------
// Main fused kernel, persistent over NIT_PER i-tiles. Smem columns stored
// pair-permuted: within each group of 8 cols, order [c0,c4,c1,c5,c2,c6,c3,c7]
// so fragment pairs (kq, kq+4) are adjacent -> LDS.64 A halves, LDS.U32 bf16x2 B.
#define AJ_STRIDE 808   // floats; ==8 mod 32 -> conflict-free 64-bit phases
#define W2S 840         // halves; bank = 4r+kq, all 32 lanes distinct
#define SMEM_MAIN ((32 * AJ_STRIDE + 12 * AJ_STRIDE) * 4 + 40 * W2S * 2 + 128)

__global__ __launch_bounds__(256, 1) void k_main(const int* __restrict__ spans,
                                                 const int* __restrict__ smask,
                                                 const float* __restrict__ b2,
                                                 float* __restrict__ out) {
    extern __shared__ char smem[];
    float* AjS = (float*)smem;                                   // [32][808]
    float* AiC = AjS + 32 * AJ_STRIDE;                           // [4][3][808]
    __nv_bfloat16* W2s = (__nv_bfloat16*)(AiC + 12 * AJ_STRIDE); // [40][840]
    unsigned char* cf = (unsigned char*)((char*)W2s + 40 * W2S * 2); // [4][32]

    const int tid = threadIdx.x;
    const int b = blockIdx.z, itc = blockIdx.y, jt = blockIdx.x;
    const int j0 = jt * 32;
    const int s = spans[b * 2], e = spans[b * 2 + 1];

    // ---- one-time prologue: Aj tile + W2 tile ----
    for (int u = tid; u < 32 * 98; u += 256) {
        int row = u / 98, g = u - row * 98;
        int j = j0 + row;
        float4 v0 = make_float4(0.f, 0.f, 0.f, 0.f), v1 = v0;
        if (j < LSEQ) {
            const float4* src = (const float4*)&g_Aj[(size_t)(b * LSEQ + j) * KP + g * 8];
            v0 = src[0];
            v1 = src[1];
        }
        float4* dst = (float4*)&AjS[row * AJ_STRIDE + g * 8];
        dst[0] = make_float4(v0.x, v1.x, v0.y, v1.y);
        dst[1] = make_float4(v0.z, v1.z, v0.w, v1.w);
    }
    for (int u = tid; u < 40 * 98; u += 256) {
        int row = u / 98, g = u - row * 98;
        uint4 v = *(const uint4*)&g_W2b[row * KP + g * 8];
        unsigned o0 = __byte_perm(v.x, v.z, 0x5410);
        unsigned o1 = __byte_perm(v.x, v.z, 0x7632);
        unsigned o2 = __byte_perm(v.y, v.w, 0x5410);
        unsigned o3 = __byte_perm(v.y, v.w, 0x7632);
        *(uint4*)((char*)W2s + ((size_t)row * W2S + g * 8) * 2) = make_uint4(o0, o1, o2, o3);
    }

    const int lane = tid & 31, w = tid >> 5;
    const int il = w >> 1, j0l = (w & 1) * 16;
    const int r = lane >> 2, kq = lane & 3;
    const int jr0 = j0l + r, jr1 = jr0 + 8;
    const int jg0 = j0 + jr0, jg1 = j0 + jr1;

    // per-thread biases (constant across it loop)
    float bb[5][2];
#pragma unroll
    for (int nt = 0; nt < 5; nt++) {
        int k0 = nt * 8 + kq * 2;
        bb[nt][0] = (k0 < NLAB) ? b2[k0] : 0.0f;
        bb[nt][1] = (k0 + 1 < NLAB) ? b2[k0 + 1] : 0.0f;
    }
    // running per-k max across all it iterations (masked entries are 0 -> init 0)
    float mx[5][2];
#pragma unroll
    for (int nt = 0; nt < 5; nt++) mx[nt][0] = mx[nt][1] = 0.0f;

    for (int t7 = 0; t7 < NIT_PER; t7++) {
        const int it = itc * NIT_PER + t7;
        const int i0 = it * 4;

        __syncthreads();  // previous iteration's compute done before AiC overwrite
        // AiC = Ai[i0+il] + Cc[c] (pair-permuted)
        for (int u = tid; u < 12 * 98; u += 256) {
            int rc = u / 98, g = u - rc * 98;
            int ill = rc / 3, c = rc - ill * 3;
            const float4* sa = (const float4*)&g_Ai[(size_t)(b * LSEQ + i0 + ill) * KP + g * 8];
            const float4* sc = (const float4*)&g_Cc[c * KP + g * 8];
            float4 a0 = sa[0], a1 = sa[1], c0 = sc[0], c1 = sc[1];
            float4 x = make_float4(a0.x + c0.x, a0.y + c0.y, a0.z + c0.z, a0.w + c0.w);
            float4 y = make_float4(a1.x + c1.x, a1.y + c1.y, a1.z + c1.z, a1.w + c1.w);
            float4* dst = (float4*)&AiC[rc * AJ_STRIDE + g * 8];
            dst[0] = make_float4(x.x, y.x, x.y, y.y);
            dst[1] = make_float4(x.z, y.z, x.w, y.w);
        }
        // c / valid flags
        for (int t = tid; t < 4 * 32; t += 256) {
            int ill = t >> 5, jl = t & 31;
            int i = i0 + ill, j = j0 + jl;
            int c = 0, valid = 0;
            if (j < LSEQ) {
                valid = (smask[i * LSEQ + j] >= 1) ? 1 : 0;
                if (s <= i && i <= j && j <= e) c = (i == s && j == e) ? 2 : 1;
            }
            cf[t] = (unsigned char)(c | (valid << 2));
        }
        __syncthreads();

        const int f0 = cf[il * 32 + jr0], f1 = cf[il * 32 + jr1];
        const float* aj0 = AjS + jr0 * AJ_STRIDE + 2 * kq;
        const float* aj1 = AjS + jr1 * AJ_STRIDE + 2 * kq;
        const float* ac0 = AiC + (il * 3 + (f0 & 3)) * AJ_STRIDE + 2 * kq;
        const float* ac1 = AiC + (il * 3 + (f1 & 3)) * AJ_STRIDE + 2 * kq;
        const char* wp = (const char*)W2s + ((size_t)r * W2S + 2 * kq) * 2;

        float acc[5][4];
#pragma unroll
        for (int nt = 0; nt < 5; nt++)
#pragma unroll
            for (int q = 0; q < 4; q++) acc[nt][q] = 0.0f;

#pragma unroll 2
        for (int ks = 0; ks < 98; ks++) {
            const int off = ks * 8;
            float2 pj0 = *(const float2*)(aj0 + off);
            float2 pc0 = *(const float2*)(ac0 + off);
            float2 pj1 = *(const float2*)(aj1 + off);
            float2 pc1 = *(const float2*)(ac1 + off);
            float a0 = fmaxf(pj0.x + pc0.x, 0.0f);
            float a2 = fmaxf(pj0.y + pc0.y, 0.0f);
            float a1 = fmaxf(pj1.x + pc1.x, 0.0f);
            float a3 = fmaxf(pj1.y + pc1.y, 0.0f);
#pragma unroll
            for (int nt = 0; nt < 5; nt++) {
                unsigned wv = *(const unsigned*)(wp + ((size_t)nt * 8 * W2S + off) * 2);
                float b0 = __uint_as_float(wv << 16);
                float b1 = __uint_as_float(wv & 0xFFFF0000u);
                mma_tf32(acc[nt], a0, a1, a2, a3, b0, b1);
            }
        }

        // epilogue: +b2, mask, store; track per-k max
        const int i = i0 + il;
        const int v0 = (f0 >> 2) & 1, v1 = (f1 >> 2) & 1;
#pragma unroll
        for (int nt = 0; nt < 5; nt++) {
            int k0 = nt * 8 + kq * 2;
            if (k0 < NLAB) {
                if (jg0 < LSEQ) {
                    float s0 = v0 ? (acc[nt][0] + bb[nt][0]) : 0.0f;
                    float s1 = v0 ? (acc[nt][1] + bb[nt][1]) : 0.0f;
                    size_t p0 = (size_t)(b * NLAB + k0) * LL + i * LSEQ + jg0;
                    out[p0] = s0;
                    out[p0 + LL] = s1;
                    mx[nt][0] = fmaxf(mx[nt][0], s0);
                    mx[nt][1] = fmaxf(mx[nt][1], s1);
                }
                if (jg1 < LSEQ) {
                    float s0 = v1 ? (acc[nt][2] + bb[nt][0]) : 0.0f;
                    float s1 = v1 ? (acc[nt][3] + bb[nt][1]) : 0.0f;
                    size_t p1 = (size_t)(b * NLAB + k0) * LL + i * LSEQ + jg1;
                    out[p1] = s0;
                    out[p1 + LL] = s1;
                    mx[nt][0] = fmaxf(mx[nt][0], s0);
                    mx[nt][1] = fmaxf(mx[nt][1], s1);
                }
            }
        }
    }

    // fold max over r-lanes (lane = r*4+kq; r lives in bits 2..4), then atomicMax.
#pragma unroll
    for (int nt = 0; nt < 5; nt++) {
#pragma unroll
        for (int q = 0; q < 2; q++) {
            float m = mx[nt][q];
            m = fmaxf(m, __shfl_xor_sync(0xFFFFFFFFu, m, 4));
            m = fmaxf(m, __shfl_xor_sync(0xFFFFFFFFu, m, 8));
            m = fmaxf(m, __shfl_xor_sync(0xFFFFFFFFu, m, 16));
            int k0 = nt * 8 + kq * 2 + q;
            if (r == 0 && k0 < NLAB)
                atomicMax(&g_maxbits[b * NLAB + k0], __float_as_uint(m));
        }
    }
}

// ---------------------------------------------------------------------------
// Partial sum of exp(x - M); 4 independent accumulator chains + 2-way load ILP.
__global__ __launch_bounds__(256) void k_sumexp(const float* __restrict__ out) {
    const int bk = blockIdx.y;
    const float4* p = (const float4*)(out + (size_t)bk * LL);
    const float M = __uint_as_float(g_maxbits[bk]);
    const float L2E = 1.4426950408889634f;
    const float nML2E = -M * L2E;
    const int STR = NPART * 256;
    float s0 = 0.f, s1 = 0.f, s2 = 0.f, s3 = 0.f;
    for (int t = blockIdx.x * 256 + threadIdx.x; t < LL4; t += 2 * STR) {
        float4 v = p[t];
        float4 u = make_float4(0.f, 0.f, 0.f, 0.f);
        int t2 = t + STR;
        bool hi = (t2 < LL4);
        if (hi) u = p[t2];
        s0 += exp2f(fmaf(v.x, L2E, nML2E));
        s1 += exp2f(fmaf(v.y, L2E, nML2E));
        s2 += exp2f(fmaf(v.z, L2E, nML2E));
        s3 += exp2f(fmaf(v.w, L2E, nML2E));
        if (hi) {
            s0 += exp2f(fmaf(u.x, L2E, nML2E));
            s1 += exp2f(fmaf(u.y, L2E, nML2E));
            s2 += exp2f(fmaf(u.z, L2E, nML2E));
            s3 += exp2f(fmaf(u.w, L2E, nML2E));
        }
    }
    float s = (s0 + s1) + (s2 + s3);
#pragma unroll
    for (int o = 16; o > 0; o >>= 1) s += __shfl_xor_sync(0xFFFFFFFFu, s, o);
    __shared__ float sm[8];
    if ((threadIdx.x & 31) == 0) sm[threadIdx.x >> 5] = s;
    __syncthreads();
    if (threadIdx.x == 0) {
        float ss = 0.f;
#pragma unroll
        for (int q = 0; q < 8; q++) ss += sm[q];
        g_psum[bk * NPART + blockIdx.x] = ss;  // fixed slot -> deterministic
    }
}

// Combine partials (fixed order) + subtract lse.
__global__ __launch_bounds__(256) void k_sub(float* __restrict__ out) {
    const int bk = blockIdx.y;
    __shared__ float lse_s;
    if (threadIdx.x == 0) {
        float M = __uint_as_float(g_maxbits[bk]);
        float s = 0.f;
#pragma unroll
        for (int q = 0; q < NPART; q++) s += g_psum[bk * NPART + q];
        lse_s = M + logf(s);
    }
    __syncthreads();
    const float lse = lse_s;
    int t = blockIdx.x * 256 + threadIdx.x;
    if (t < LL4) {
        float4* p = (float4*)(out + (size_t)bk * LL);
        float4 v = p[t];
        v.x -= lse;
        v.y -= lse;
        v.z -= lse;
        v.w -= lse;
        p[t] = v;
    }
}

// ---------------------------------------------------------------------------
extern "C" void kernel_launch(void* const* d_in, const int* in_sizes, int n_in,
                              void* d_out, int out_size) {
    const float* hidden = (const float*)d_in[0];
    const int* spans = (const int*)d_in[1];
    const int* smask = (const int*)d_in[2];
    const float* W1 = (const float*)d_in[3];
    const float* b1 = (const float*)d_in[4];
    const float* W2 = (const float*)d_in[5];
    const float* b2 = (const float*)d_in[6];
    float* out = (float*)d_out;

    cudaFuncSetAttribute(k_main, cudaFuncAttributeMaxDynamicSharedMemorySize, SMEM_MAIN);

    k_prep<<<256, 256>>>(W1, b1, W2);
    k_ph1<<<dim3(25, 8), 128>>>(hidden);
    k_main<<<dim3(8, 9, 2), 256, SMEM_MAIN>>>(spans, smask, b2, out);
    k_sumexp<<<dim3(NPART, BATCH * NLAB), 256>>>(out);
    k_sub<<<dim3((LL4 + 255) / 256, BATCH * NLAB), 256>>>(out);
}